// round 8
// baseline (speedup 1.0000x reference)
#include <cuda_runtime.h>
#include <cuda_bf16.h>
#include <stdint.h>

#define D             128
#define TWO_D         256
#define WARPS         8
#define THREADS       (WARPS * 32)
#define BLOCKS        760              // 152 SMs x 5 blocks/SM -> single full wave
#define TOTAL_WARPS   (BLOCKS * WARPS) // 6080
#define PSLOTS        5                // pair-slots in ring (2 rows each -> 10 rows, 40KB)
#define DEPTH_P       4                // pair-groups in flight (8 rows outstanding)

__global__ void zero_out_kernel(float4* __restrict__ out, int n4) {
    int i = blockIdx.x * blockDim.x + threadIdx.x;
    if (i < n4) out[i] = make_float4(0.f, 0.f, 0.f, 0.f);
}

__device__ __forceinline__ void cp_async16(void* smem_dst, const void* gmem_src) {
    uint32_t s = (uint32_t)__cvta_generic_to_shared(smem_dst);
    asm volatile("cp.async.cg.shared.global [%0], [%1], 16;\n"
                 :: "r"(s), "l"(gmem_src) : "memory");
}
__device__ __forceinline__ void cp_commit() {
    asm volatile("cp.async.commit_group;\n" ::: "memory");
}
__device__ __forceinline__ void cp_wait3() {
    asm volatile("cp.async.wait_group 3;\n" ::: "memory");
}
__device__ __forceinline__ void cp_wait0() {
    asm volatile("cp.async.wait_group 0;\n" ::: "memory");
}

__device__ __forceinline__ void flush_acc(float* __restrict__ out, int b, int lane4,
                                          float4& a0, float4& a1) {
    float* p0 = out + (size_t)b * TWO_D + lane4;
    atomicAdd(p0 + 0, a0.x);
    atomicAdd(p0 + 1, a0.y);
    atomicAdd(p0 + 2, a0.z);
    atomicAdd(p0 + 3, a0.w);
    float* p1 = p0 + D;
    atomicAdd(p1 + 0, a1.x);
    atomicAdd(p1 + 1, a1.y);
    atomicAdd(p1 + 2, a1.z);
    atomicAdd(p1 + 3, a1.w);
    a0 = make_float4(0.f, 0.f, 0.f, 0.f);
    a1 = make_float4(0.f, 0.f, 0.f, 0.f);
}

__global__ __launch_bounds__(THREADS, 5)
void pool_kernel(const float* __restrict__ node_rep,
                 const int*   __restrict__ batch_ids,
                 const int*   __restrict__ mol_idx,
                 float*       __restrict__ out,
                 int n_rows,
                 int rows_per_warp) {
    __shared__ float4 buf[WARPS][PSLOTS][2][32];   // 40 KB

    const int warp  = threadIdx.x >> 5;
    const int lane  = threadIdx.x & 31;
    const int lane4 = lane << 2;

    const int gwarp = blockIdx.x * WARPS + warp;
    int cs = gwarp * rows_per_warp;
    int ce = cs + rows_per_warp;
    if (cs >= n_rows) return;
    if (ce > n_rows) ce = n_rows;
    const int nchunk = ce - cs;
    const int npairs = nchunk >> 1;

    const float4* nr = reinterpret_cast<const float4*>(node_rep);

    // ---- prologue: fill pipeline with DEPTH_P pair-groups ----
    int issued = 0;
    #pragma unroll
    for (int s = 0; s < DEPTH_P; s++) {
        if (issued < nchunk) {
            cp_async16(&buf[warp][s][0][lane], nr + (size_t)(cs + issued) * (D / 4) + lane);
            issued++;
        }
        if (issued < nchunk) {
            cp_async16(&buf[warp][s][1][lane], nr + (size_t)(cs + issued) * (D / 4) + lane);
            issued++;
        }
        cp_commit();    // empty groups keep the count invariant
    }

    float4 acc0 = make_float4(0.f, 0.f, 0.f, 0.f);
    float4 acc1 = make_float4(0.f, 0.f, 0.f, 0.f);
    int cur_b = -1;

    int rslot = 0;              // pair-slot being consumed
    int wslot = DEPTH_P;        // pair-slot being filled (= 4, free after prologue)

    // ---- main loop: 2 rows per iteration, 8 rows in flight ----
    for (int i = 0; i < npairs; i++) {
        const int rbase = cs + 2 * i;
        const int b0 = __ldg(batch_ids + rbase);
        const int m0 = __ldg(mol_idx   + rbase);
        const int b1 = __ldg(batch_ids + rbase + 1);
        const int m1 = __ldg(mol_idx   + rbase + 1);

        cp_wait3();                              // pair i's group complete
        const float4 v0 = buf[warp][rslot][0][lane];
        const float4 v1 = buf[warp][rslot][1][lane];

        // prefetch next pair into wslot (freed last iteration)
        if (issued < nchunk) {
            cp_async16(&buf[warp][wslot][0][lane], nr + (size_t)(cs + issued) * (D / 4) + lane);
            issued++;
        }
        if (issued < nchunk) {
            cp_async16(&buf[warp][wslot][1][lane], nr + (size_t)(cs + issued) * (D / 4) + lane);
            issued++;
        }
        cp_commit();

        if (b0 != cur_b) { if (cur_b >= 0) flush_acc(out, cur_b, lane4, acc0, acc1); cur_b = b0; }
        if (m0 == 0) { acc0.x += v0.x; acc0.y += v0.y; acc0.z += v0.z; acc0.w += v0.w; }
        else         { acc1.x += v0.x; acc1.y += v0.y; acc1.z += v0.z; acc1.w += v0.w; }

        if (b1 != cur_b) { flush_acc(out, cur_b, lane4, acc0, acc1); cur_b = b1; }
        if (m1 == 0) { acc0.x += v1.x; acc0.y += v1.y; acc0.z += v1.z; acc0.w += v1.w; }
        else         { acc1.x += v1.x; acc1.y += v1.y; acc1.z += v1.z; acc1.w += v1.w; }

        rslot = (rslot + 1 == PSLOTS) ? 0 : rslot + 1;   // cheap ring advance, no mod
        wslot = (wslot + 1 == PSLOTS) ? 0 : wslot + 1;
    }

    // ---- odd tail row (issued as row0 of pair-group npairs) ----
    if (nchunk & 1) {
        const int rlast = cs + nchunk - 1;
        const int b = __ldg(batch_ids + rlast);
        const int m = __ldg(mol_idx   + rlast);
        cp_wait0();
        const float4 v = buf[warp][rslot][0][lane];
        if (b != cur_b) { if (cur_b >= 0) flush_acc(out, cur_b, lane4, acc0, acc1); cur_b = b; }
        if (m == 0) { acc0.x += v.x; acc0.y += v.y; acc0.z += v.z; acc0.w += v.w; }
        else        { acc1.x += v.x; acc1.y += v.y; acc1.z += v.z; acc1.w += v.w; }
    }

    if (cur_b >= 0) flush_acc(out, cur_b, lane4, acc0, acc1);
}

extern "C" void kernel_launch(void* const* d_in, const int* in_sizes, int n_in,
                              void* d_out, int out_size) {
    const float* node_rep  = (const float*)d_in[0];
    const int*   batch_ids = (const int*)  d_in[1];
    const int*   mol_idx   = (const int*)  d_in[2];
    float*       out       = (float*)      d_out;

    const int n_rows = in_sizes[1];

    int rpw = (n_rows + TOTAL_WARPS - 1) / TOTAL_WARPS;
    rpw = (rpw + 3) & ~3;

    {
        int n4 = out_size / 4;
        int threads = 256;
        int blocks  = (n4 + threads - 1) / threads;
        zero_out_kernel<<<blocks, threads>>>((float4*)out, n4);
    }
    pool_kernel<<<BLOCKS, THREADS>>>(node_rep, batch_ids, mol_idx, out, n_rows, rpw);
}

// round 9
// speedup vs baseline: 1.0481x; 1.0481x over previous
#include <cuda_runtime.h>
#include <cuda_bf16.h>
#include <stdint.h>

#define D             128
#define TWO_D         256
#define WARPS         8
#define THREADS       (WARPS * 32)
#define BLOCKS        760              // 152 SMs x 5 blocks/SM -> single full wave
#define TOTAL_WARPS   (BLOCKS * WARPS) // 6080
#define UNROLL        4

__device__ __forceinline__ void flush_acc(float* __restrict__ out, int b, int lane4,
                                          float4& a0, float4& a1) {
    float* p0 = out + (size_t)b * TWO_D + lane4;
    atomicAdd(p0 + 0, a0.x);
    atomicAdd(p0 + 1, a0.y);
    atomicAdd(p0 + 2, a0.z);
    atomicAdd(p0 + 3, a0.w);
    float* p1 = p0 + D;
    atomicAdd(p1 + 0, a1.x);
    atomicAdd(p1 + 1, a1.y);
    atomicAdd(p1 + 2, a1.z);
    atomicAdd(p1 + 3, a1.w);
    a0 = make_float4(0.f, 0.f, 0.f, 0.f);
    a1 = make_float4(0.f, 0.f, 0.f, 0.f);
}

__global__ __launch_bounds__(THREADS, 5)
void pool_kernel(const float* __restrict__ node_rep,
                 const int*   __restrict__ batch_ids,
                 const int*   __restrict__ mol_idx,
                 float*       __restrict__ out,
                 int n_rows,
                 int rows_per_warp) {         // multiple of 4
    const int warp  = threadIdx.x >> 5;
    const int lane  = threadIdx.x & 31;
    const int lane4 = lane << 2;

    // perfectly balanced: one contiguous 4-aligned chunk per warp, single wave
    const int gwarp = blockIdx.x * WARPS + warp;
    int cs = gwarp * rows_per_warp;
    int ce = cs + rows_per_warp;
    if (cs >= n_rows) return;
    if (ce > n_rows) ce = n_rows;

    float4 acc0 = make_float4(0.f, 0.f, 0.f, 0.f);
    float4 acc1 = make_float4(0.f, 0.f, 0.f, 0.f);
    int cur_b = -1;

    const float4* nr = reinterpret_cast<const float4*>(node_rep);

    int r = cs;
    for (; r + (UNROLL - 1) < ce; r += UNROLL) {
        const int4 bb = __ldg(reinterpret_cast<const int4*>(batch_ids + r));
        const int4 mm = __ldg(reinterpret_cast<const int4*>(mol_idx   + r));
        // streaming (evict-first) reads: node_rep is strictly read-once
        const float4 v0 = __ldcs(nr + (size_t)(r + 0) * (D / 4) + lane);
        const float4 v1 = __ldcs(nr + (size_t)(r + 1) * (D / 4) + lane);
        const float4 v2 = __ldcs(nr + (size_t)(r + 2) * (D / 4) + lane);
        const float4 v3 = __ldcs(nr + (size_t)(r + 3) * (D / 4) + lane);

        if (bb.x != cur_b) { if (cur_b >= 0) flush_acc(out, cur_b, lane4, acc0, acc1); cur_b = bb.x; }
        if (mm.x == 0) { acc0.x += v0.x; acc0.y += v0.y; acc0.z += v0.z; acc0.w += v0.w; }
        else           { acc1.x += v0.x; acc1.y += v0.y; acc1.z += v0.z; acc1.w += v0.w; }

        if (bb.y != cur_b) { flush_acc(out, cur_b, lane4, acc0, acc1); cur_b = bb.y; }
        if (mm.y == 0) { acc0.x += v1.x; acc0.y += v1.y; acc0.z += v1.z; acc0.w += v1.w; }
        else           { acc1.x += v1.x; acc1.y += v1.y; acc1.z += v1.z; acc1.w += v1.w; }

        if (bb.z != cur_b) { flush_acc(out, cur_b, lane4, acc0, acc1); cur_b = bb.z; }
        if (mm.z == 0) { acc0.x += v2.x; acc0.y += v2.y; acc0.z += v2.z; acc0.w += v2.w; }
        else           { acc1.x += v2.x; acc1.y += v2.y; acc1.z += v2.z; acc1.w += v2.w; }

        if (bb.w != cur_b) { flush_acc(out, cur_b, lane4, acc0, acc1); cur_b = bb.w; }
        if (mm.w == 0) { acc0.x += v3.x; acc0.y += v3.y; acc0.z += v3.z; acc0.w += v3.w; }
        else           { acc1.x += v3.x; acc1.y += v3.y; acc1.z += v3.z; acc1.w += v3.w; }
    }
    for (; r < ce; r++) {
        const int b = __ldg(batch_ids + r);
        const int m = __ldg(mol_idx   + r);
        const float4 v = __ldcs(nr + (size_t)r * (D / 4) + lane);
        if (b != cur_b) { if (cur_b >= 0) flush_acc(out, cur_b, lane4, acc0, acc1); cur_b = b; }
        if (m == 0) { acc0.x += v.x; acc0.y += v.y; acc0.z += v.z; acc0.w += v.w; }
        else        { acc1.x += v.x; acc1.y += v.y; acc1.z += v.z; acc1.w += v.w; }
    }

    if (cur_b >= 0) flush_acc(out, cur_b, lane4, acc0, acc1);
}

extern "C" void kernel_launch(void* const* d_in, const int* in_sizes, int n_in,
                              void* d_out, int out_size) {
    const float* node_rep  = (const float*)d_in[0];
    const int*   batch_ids = (const int*)  d_in[1];
    const int*   mol_idx   = (const int*)  d_in[2];
    float*       out       = (float*)      d_out;

    const int n_rows = in_sizes[1];

    // rows per warp: balanced across TOTAL_WARPS, rounded up to multiple of 4
    int rpw = (n_rows + TOTAL_WARPS - 1) / TOTAL_WARPS;
    rpw = (rpw + 3) & ~3;

    // zero the poisoned output via a memset node (cheaper than a kernel launch)
    cudaMemsetAsync(out, 0, (size_t)out_size * sizeof(float));

    pool_kernel<<<BLOCKS, THREADS>>>(node_rep, batch_ids, mol_idx, out, n_rows, rpw);
}

// round 10
// speedup vs baseline: 1.0526x; 1.0043x over previous
#include <cuda_runtime.h>
#include <cuda_bf16.h>
#include <stdint.h>

#define D             128
#define TWO_D         256
#define WARPS         8
#define THREADS       (WARPS * 32)
#define BLOCKS        760              // 152 SMs x 5 blocks/SM -> single full wave
#define TOTAL_WARPS   (BLOCKS * WARPS) // 6080
#define UNROLL        4

__global__ void zero_out_kernel(float4* __restrict__ out, int n4) {
    int i = blockIdx.x * blockDim.x + threadIdx.x;
    if (i < n4) out[i] = make_float4(0.f, 0.f, 0.f, 0.f);
}

__device__ __forceinline__ void flush_acc(float* __restrict__ out, int b, int lane4,
                                          float4& a0, float4& a1) {
    float* p0 = out + (size_t)b * TWO_D + lane4;
    atomicAdd(p0 + 0, a0.x);
    atomicAdd(p0 + 1, a0.y);
    atomicAdd(p0 + 2, a0.z);
    atomicAdd(p0 + 3, a0.w);
    float* p1 = p0 + D;
    atomicAdd(p1 + 0, a1.x);
    atomicAdd(p1 + 1, a1.y);
    atomicAdd(p1 + 2, a1.z);
    atomicAdd(p1 + 3, a1.w);
    a0 = make_float4(0.f, 0.f, 0.f, 0.f);
    a1 = make_float4(0.f, 0.f, 0.f, 0.f);
}

__global__ __launch_bounds__(THREADS, 5)
void pool_kernel(const float* __restrict__ node_rep,
                 const int*   __restrict__ batch_ids,
                 const int*   __restrict__ mol_idx,
                 float*       __restrict__ out,
                 int n_rows,
                 int rows_per_warp) {         // multiple of 4
    const int warp  = threadIdx.x >> 5;
    const int lane  = threadIdx.x & 31;
    const int lane4 = lane << 2;

    // perfectly balanced: one contiguous 4-aligned chunk per warp, single wave
    const int gwarp = blockIdx.x * WARPS + warp;
    int cs = gwarp * rows_per_warp;
    int ce = cs + rows_per_warp;
    if (cs >= n_rows) return;
    if (ce > n_rows) ce = n_rows;

    float4 acc0 = make_float4(0.f, 0.f, 0.f, 0.f);
    float4 acc1 = make_float4(0.f, 0.f, 0.f, 0.f);
    int cur_b = -1;

    const float4* nr = reinterpret_cast<const float4*>(node_rep);

    int r = cs;
    for (; r + (UNROLL - 1) < ce; r += UNROLL) {
        const int4 bb = __ldg(reinterpret_cast<const int4*>(batch_ids + r));
        const int4 mm = __ldg(reinterpret_cast<const int4*>(mol_idx   + r));
        // streaming (evict-first) reads: node_rep is strictly read-once
        const float4 v0 = __ldcs(nr + (size_t)(r + 0) * (D / 4) + lane);
        const float4 v1 = __ldcs(nr + (size_t)(r + 1) * (D / 4) + lane);
        const float4 v2 = __ldcs(nr + (size_t)(r + 2) * (D / 4) + lane);
        const float4 v3 = __ldcs(nr + (size_t)(r + 3) * (D / 4) + lane);

        if (bb.x != cur_b) { if (cur_b >= 0) flush_acc(out, cur_b, lane4, acc0, acc1); cur_b = bb.x; }
        if (mm.x == 0) { acc0.x += v0.x; acc0.y += v0.y; acc0.z += v0.z; acc0.w += v0.w; }
        else           { acc1.x += v0.x; acc1.y += v0.y; acc1.z += v0.z; acc1.w += v0.w; }

        if (bb.y != cur_b) { flush_acc(out, cur_b, lane4, acc0, acc1); cur_b = bb.y; }
        if (mm.y == 0) { acc0.x += v1.x; acc0.y += v1.y; acc0.z += v1.z; acc0.w += v1.w; }
        else           { acc1.x += v1.x; acc1.y += v1.y; acc1.z += v1.z; acc1.w += v1.w; }

        if (bb.z != cur_b) { flush_acc(out, cur_b, lane4, acc0, acc1); cur_b = bb.z; }
        if (mm.z == 0) { acc0.x += v2.x; acc0.y += v2.y; acc0.z += v2.z; acc0.w += v2.w; }
        else           { acc1.x += v2.x; acc1.y += v2.y; acc1.z += v2.z; acc1.w += v2.w; }

        if (bb.w != cur_b) { flush_acc(out, cur_b, lane4, acc0, acc1); cur_b = bb.w; }
        if (mm.w == 0) { acc0.x += v3.x; acc0.y += v3.y; acc0.z += v3.z; acc0.w += v3.w; }
        else           { acc1.x += v3.x; acc1.y += v3.y; acc1.z += v3.z; acc1.w += v3.w; }
    }
    for (; r < ce; r++) {
        const int b = __ldg(batch_ids + r);
        const int m = __ldg(mol_idx   + r);
        const float4 v = __ldcs(nr + (size_t)r * (D / 4) + lane);
        if (b != cur_b) { if (cur_b >= 0) flush_acc(out, cur_b, lane4, acc0, acc1); cur_b = b; }
        if (m == 0) { acc0.x += v.x; acc0.y += v.y; acc0.z += v.z; acc0.w += v.w; }
        else        { acc1.x += v.x; acc1.y += v.y; acc1.z += v.z; acc1.w += v.w; }
    }

    if (cur_b >= 0) flush_acc(out, cur_b, lane4, acc0, acc1);
}

extern "C" void kernel_launch(void* const* d_in, const int* in_sizes, int n_in,
                              void* d_out, int out_size) {
    const float* node_rep  = (const float*)d_in[0];
    const int*   batch_ids = (const int*)  d_in[1];
    const int*   mol_idx   = (const int*)  d_in[2];
    float*       out       = (float*)      d_out;

    const int n_rows = in_sizes[1];

    // rows per warp: balanced across TOTAL_WARPS, rounded up to multiple of 4
    int rpw = (n_rows + TOTAL_WARPS - 1) / TOTAL_WARPS;
    rpw = (rpw + 3) & ~3;

    {
        int n4 = out_size / 4;
        int threads = 256;
        int blocks  = (n4 + threads - 1) / threads;
        zero_out_kernel<<<blocks, threads>>>((float4*)out, n4);
    }
    pool_kernel<<<BLOCKS, THREADS>>>(node_rep, batch_ids, mol_idx, out, n_rows, rpw);
}